// round 16
// baseline (speedup 1.0000x reference)
#include <cuda_runtime.h>

// SmartDoorClassifierv1 — fused CNN (LIF collapses: alpha = exp(-200) == 0 in fp32).
// Round 15: kernel is AT the scalar-FFMA pipe roofline (3914 FFMA x rt2 ~= whole
// duration). Convert stages 2+3 to packed fma.rn.f32x2 (pair over dx):
//  - weights pre-duplicated (w,w) in smem -> ulonglong2 broadcast loads, no
//    per-use marshaling (R2's mistake #1)
//  - acc/data pairs natural float2-aligned (1 pack per patch row) at (256,3)
//    with bounded scope (R2's mistake #2: global pairing blew registers)
// Per-lane accumulate order identical to scalar -> bitwise-identical output.

#define THREADS 256
typedef unsigned long long u64;

__device__ __forceinline__ u64 pk(float lo, float hi) {
    u64 r; asm("mov.b64 %0, {%1, %2};" : "=l"(r) : "f"(lo), "f"(hi)); return r;
}
__device__ __forceinline__ float2 upk(u64 v) {
    float2 f; asm("mov.b64 {%0, %1}, %2;" : "=f"(f.x), "=f"(f.y) : "l"(v)); return f;
}
__device__ __forceinline__ void fma2(u64& d, u64 a, u64 b) {
    asm("fma.rn.f32x2 %0, %1, %2, %0;" : "+l"(d) : "l"(a), "l"(b));
}

// dynamic smem layout (float indices)
//  p1p  : 9540  (8 planes, stride 1188, shared zero halos, row stride 36)
//  p2p  : 2466  (8 planes, stride 306, shared zero halos)
//  p3   : 512
//  sw1  : 64    (scalar, stage-1)
//  sw2d : 1280  duplicated pairs: (oc*8+ic)*20 + 2k (+1)  [broadcast reads]
//  sw3d : 1312  duplicated pairs: oc*164 + ic*20 + 2k (+1) [ocg-padded]
//  red  : 16
#define OFF_P1   0
#define OFF_P2   9540
#define OFF_P3   12008
#define OFF_W1   12520
#define OFF_W2D  12584
#define OFF_W3D  13864
#define OFF_RED  15176
#define SMEM_FLOATS (OFF_RED + 16)   // 15192 floats = 60768 B

#define P1_RS   36
#define P1_PL   1188
#define P2_RS   18
#define P2_PL   306

__global__ __launch_bounds__(THREADS, 3)
void snn_fused_kernel(const float* __restrict__ x,
                      const float* __restrict__ w1,
                      const float* __restrict__ w2,
                      const float* __restrict__ w3,
                      const float* __restrict__ wfc,
                      float* __restrict__ out)
{
    extern __shared__ float smem[];
    float* p1p  = smem + OFF_P1;
    float* p2p  = smem + OFF_P2;
    float* p3   = smem + OFF_P3;
    float* sw1  = smem + OFF_W1;
    float* sw2d = smem + OFF_W2D;
    float* sw3d = smem + OFF_W3D;
    float* red  = smem + OFF_RED;

    const int tid = threadIdx.x;
    const int n   = blockIdx.x;

    // ---- init: weights (sw1 scalar; sw2/sw3 duplicated pairs) + halo fill ----
    if (tid < 64) sw1[tid] = w1[tid];
    for (int i = tid; i < 576; i += THREADS) {
        int oc = i / 72, rem = i % 72, ic = rem / 9, k = rem % 9;
        float v2 = w2[i], v3 = w3[i];
        int b2 = (oc * 8 + ic) * 20 + 2 * k;
        sw2d[b2] = v2; sw2d[b2 + 1] = v2;
        int b3 = oc * 164 + ic * 20 + 2 * k;
        sw3d[b3] = v3; sw3d[b3 + 1] = v3;
    }
    for (int i = tid; i < 9 * 34; i += THREADS) {
        int b = i / 34, c = i % 34;
        p1p[b * P1_PL + c] = 0.f;
    }
    for (int i = tid; i < 8 * 32; i += THREADS) {
        int ic = i / 32, r = (i % 32) + 1;
        p1p[ic * P1_PL + r * P1_RS] = 0.f;
        p1p[ic * P1_PL + r * P1_RS + 33] = 0.f;
    }
    for (int i = tid; i < 9 * 18; i += THREADS) {
        int b = i / 18, c = i % 18;
        p2p[b * P2_PL + c] = 0.f;
    }
    for (int i = tid; i < 8 * 16; i += THREADS) {
        int ic = i / 16, r = (i % 16) + 1;
        p2p[ic * P2_PL + r * P2_RS] = 0.f;
        p2p[ic * P2_PL + r * P2_RS + 17] = 0.f;
    }
    __syncthreads();

    // ================= Stage 1: conv1(2x2,s2) + floor(relu) + pool2 =========
    // (scalar — validated form; it-loop unroll 1 bounds register live range)
    const float* xb = x + (size_t)n * (2 * 128 * 128);
    #pragma unroll 1
    for (int it = 0; it < 4; it++) {
        int pos = tid + it * THREADS;          // 0..1023
        int py = pos >> 5, px = pos & 31;
        const float* src0 = xb + (4 * py) * 128 + 4 * px;   // ch0
        const float* src1 = src0 + 16384;                   // ch1
        float4 c0r0 = *reinterpret_cast<const float4*>(src0);
        float4 c0r1 = *reinterpret_cast<const float4*>(src0 + 128);
        float4 c0r2 = *reinterpret_cast<const float4*>(src0 + 256);
        float4 c0r3 = *reinterpret_cast<const float4*>(src0 + 384);
        float4 c1r0 = *reinterpret_cast<const float4*>(src1);
        float4 c1r1 = *reinterpret_cast<const float4*>(src1 + 128);
        float4 c1r2 = *reinterpret_cast<const float4*>(src1 + 256);
        float4 c1r3 = *reinterpret_cast<const float4*>(src1 + 384);

        float* dst = p1p + (py + 1) * P1_RS + (px + 1);
        #pragma unroll
        for (int oc = 0; oc < 8; oc++) {
            const float* wb = sw1 + oc * 8;
            float4 wA = *reinterpret_cast<const float4*>(wb);      // ch0 2x2
            float4 wB = *reinterpret_cast<const float4*>(wb + 4);  // ch1 2x2
            float v00, v01, v10, v11;
            v00 = c0r0.x * wA.x;               v01 = c0r0.z * wA.x;
            v00 = fmaf(c0r0.y, wA.y, v00);     v01 = fmaf(c0r0.w, wA.y, v01);
            v00 = fmaf(c0r1.x, wA.z, v00);     v01 = fmaf(c0r1.z, wA.z, v01);
            v00 = fmaf(c0r1.y, wA.w, v00);     v01 = fmaf(c0r1.w, wA.w, v01);
            v00 = fmaf(c1r0.x, wB.x, v00);     v01 = fmaf(c1r0.z, wB.x, v01);
            v00 = fmaf(c1r0.y, wB.y, v00);     v01 = fmaf(c1r0.w, wB.y, v01);
            v00 = fmaf(c1r1.x, wB.z, v00);     v01 = fmaf(c1r1.z, wB.z, v01);
            v00 = fmaf(c1r1.y, wB.w, v00);     v01 = fmaf(c1r1.w, wB.w, v01);

            v10 = c0r2.x * wA.x;               v11 = c0r2.z * wA.x;
            v10 = fmaf(c0r2.y, wA.y, v10);     v11 = fmaf(c0r2.w, wA.y, v11);
            v10 = fmaf(c0r3.x, wA.z, v10);     v11 = fmaf(c0r3.z, wA.z, v11);
            v10 = fmaf(c0r3.y, wA.w, v10);     v11 = fmaf(c0r3.w, wA.w, v11);
            v10 = fmaf(c1r2.x, wB.x, v10);     v11 = fmaf(c1r2.z, wB.x, v11);
            v10 = fmaf(c1r2.y, wB.y, v10);     v11 = fmaf(c1r2.w, wB.y, v11);
            v10 = fmaf(c1r3.x, wB.z, v10);     v11 = fmaf(c1r3.z, wB.z, v11);
            v10 = fmaf(c1r3.y, wB.w, v10);     v11 = fmaf(c1r3.w, wB.w, v11);

            float m = fmaxf(fmaxf(floorf(fmaxf(v00, 0.f)),
                                  floorf(fmaxf(v01, 0.f))),
                            fmaxf(floorf(fmaxf(v10, 0.f)),
                                  floorf(fmaxf(v11, 0.f))));
            dst[oc * P1_PL] = m;
        }
    }
    __syncthreads();

    // ================= Stage 2: conv2(3x3,p1) + floor(relu) + pool2 =========
    // Thread = 1 pooled position x 8 oc; packed f32x2 over dx.
    // acc[8][2] u64 (lanes = the 2 adjacent conv outputs), patch pairs from
    // natural float2 loads (+1 pack/row), duplicated weight pairs broadcast.
    {
        int py = tid >> 4, px = tid & 15;
        u64 acc[8][2];
        #pragma unroll
        for (int o = 0; o < 8; o++) { acc[o][0] = 0ull; acc[o][1] = 0ull; }

        #pragma unroll 1
        for (int ic = 0; ic < 8; ic++) {
            const float* base = p1p + ic * P1_PL + (2 * py) * P1_RS + 2 * px;
            u64 pr[4][3];
            #pragma unroll
            for (int r = 0; r < 4; r++) {
                float2 a = *reinterpret_cast<const float2*>(base + r * P1_RS);
                float2 b = *reinterpret_cast<const float2*>(base + r * P1_RS + 2);
                pr[r][0] = pk(a.x, a.y);
                pr[r][1] = pk(a.y, b.x);
                pr[r][2] = pk(b.x, b.y);
            }
            #pragma unroll
            for (int o = 0; o < 8; o++) {
                const u64* wb = reinterpret_cast<const u64*>(sw2d + (o * 8 + ic) * 20);
                ulonglong2 wv0 = *reinterpret_cast<const ulonglong2*>(wb);      // k0,k1
                ulonglong2 wv1 = *reinterpret_cast<const ulonglong2*>(wb + 2);  // k2,k3
                ulonglong2 wv2 = *reinterpret_cast<const ulonglong2*>(wb + 4);  // k4,k5
                ulonglong2 wv3 = *reinterpret_cast<const ulonglong2*>(wb + 6);  // k6,k7
                u64 w8 = wb[8];
                #pragma unroll
                for (int e = 0; e < 2; e++) {
                    u64 a = acc[o][e];
                    fma2(a, pr[e + 0][0], wv0.x);
                    fma2(a, pr[e + 0][1], wv0.y);
                    fma2(a, pr[e + 0][2], wv1.x);
                    fma2(a, pr[e + 1][0], wv1.y);
                    fma2(a, pr[e + 1][1], wv2.x);
                    fma2(a, pr[e + 1][2], wv2.y);
                    fma2(a, pr[e + 2][0], wv3.x);
                    fma2(a, pr[e + 2][1], wv3.y);
                    fma2(a, pr[e + 2][2], w8);
                    acc[o][e] = a;
                }
            }
        }
        float* dst = p2p + (py + 1) * P2_RS + (px + 1);
        #pragma unroll
        for (int o = 0; o < 8; o++) {
            float2 f0 = upk(acc[o][0]);
            float2 f1 = upk(acc[o][1]);
            float m = fmaxf(fmaxf(floorf(fmaxf(f0.x, 0.f)),
                                  floorf(fmaxf(f0.y, 0.f))),
                            fmaxf(floorf(fmaxf(f1.x, 0.f)),
                                  floorf(fmaxf(f1.y, 0.f))));
            dst[o * P2_PL] = m;
        }
    }
    __syncthreads();

    // ================= Stage 3: conv3(3x3,p2) + floor(relu) + pool2 =========
    // 64 pooled positions; 4 threads/pos, 2 oc each; packed f32x2 over dx.
    // sw3d oc stride 164 -> the 4 ocg lanes hit distinct bank quads.
    {
        int pos = tid >> 2;                // 0..63
        int ocg = tid & 3;
        int py = pos >> 3, px = pos & 7;
        u64 acc[2][2];                     // [j][dy], lanes = dx
        acc[0][0] = acc[0][1] = acc[1][0] = acc[1][1] = 0ull;

        #pragma unroll 1
        for (int ic = 0; ic < 8; ic++) {
            const float* base = p2p + ic * P2_PL + (2 * py) * P2_RS + 2 * px;
            u64 pr[4][3];
            #pragma unroll
            for (int r = 0; r < 4; r++) {
                float2 a = *reinterpret_cast<const float2*>(base + r * P2_RS);
                float2 b = *reinterpret_cast<const float2*>(base + r * P2_RS + 2);
                pr[r][0] = pk(a.x, a.y);
                pr[r][1] = pk(a.y, b.x);
                pr[r][2] = pk(b.x, b.y);
            }
            #pragma unroll
            for (int j = 0; j < 2; j++) {
                const u64* wb = reinterpret_cast<const u64*>(
                    sw3d + (ocg * 2 + j) * 164 + ic * 20);
                ulonglong2 wv0 = *reinterpret_cast<const ulonglong2*>(wb);
                ulonglong2 wv1 = *reinterpret_cast<const ulonglong2*>(wb + 2);
                ulonglong2 wv2 = *reinterpret_cast<const ulonglong2*>(wb + 4);
                ulonglong2 wv3 = *reinterpret_cast<const ulonglong2*>(wb + 6);
                u64 w8 = wb[8];
                #pragma unroll
                for (int dy = 0; dy < 2; dy++) {
                    u64 a = acc[j][dy];
                    fma2(a, pr[dy + 0][0], wv0.x);
                    fma2(a, pr[dy + 0][1], wv0.y);
                    fma2(a, pr[dy + 0][2], wv1.x);
                    fma2(a, pr[dy + 1][0], wv1.y);
                    fma2(a, pr[dy + 1][1], wv2.x);
                    fma2(a, pr[dy + 1][2], wv2.y);
                    fma2(a, pr[dy + 2][0], wv3.x);
                    fma2(a, pr[dy + 2][1], wv3.y);
                    fma2(a, pr[dy + 2][2], w8);
                    acc[j][dy] = a;
                }
            }
        }
        #pragma unroll
        for (int j = 0; j < 2; j++) {
            int oc = ocg * 2 + j;
            float2 f0 = upk(acc[j][0]);
            float2 f1 = upk(acc[j][1]);
            float m = fmaxf(fmaxf(floorf(fmaxf(f0.x, 0.f)),
                                  floorf(fmaxf(f0.y, 0.f))),
                            fmaxf(floorf(fmaxf(f1.x, 0.f)),
                                  floorf(fmaxf(f1.y, 0.f))));
            p3[oc * 64 + py * 8 + px] = m;     // flatten order c*64 + y*8 + x
        }
    }
    __syncthreads();

    // ================= Stage 4: fc (512 -> 2) ===============================
    {
        float a0 = 0.f, a1 = 0.f;
        #pragma unroll
        for (int k = 0; k < 2; k++) {
            int j = tid + k * THREADS;         // 0..511
            float v = p3[j];
            a0 = fmaf(v, wfc[j],       a0);
            a1 = fmaf(v, wfc[512 + j], a1);
        }
        #pragma unroll
        for (int off = 16; off > 0; off >>= 1) {
            a0 += __shfl_down_sync(0xffffffffu, a0, off);
            a1 += __shfl_down_sync(0xffffffffu, a1, off);
        }
        if ((tid & 31) == 0) {
            red[tid >> 5]       = a0;
            red[8 + (tid >> 5)] = a1;
        }
        __syncthreads();
        if (tid == 0) {
            float s0 = 0.f, s1 = 0.f;
            #pragma unroll
            for (int i = 0; i < 8; i++) { s0 += red[i]; s1 += red[8 + i]; }
            out[n * 2 + 0] = s0;
            out[n * 2 + 1] = s1;
        }
    }
}

extern "C" void kernel_launch(void* const* d_in, const int* in_sizes, int n_in,
                              void* d_out, int out_size)
{
    const float* x   = (const float*)d_in[0];
    const float* w1  = (const float*)d_in[1];
    const float* w2  = (const float*)d_in[2];
    const float* w3  = (const float*)d_in[3];
    const float* wfc = (const float*)d_in[4];
    int nsamples = in_sizes[0] / (2 * 128 * 128);   // 1024

    size_t smem_bytes = SMEM_FLOATS * sizeof(float);  // 60768 B (~59.3 KB)
    cudaFuncSetAttribute(snn_fused_kernel,
                         cudaFuncAttributeMaxDynamicSharedMemorySize,
                         (int)smem_bytes);
    snn_fused_kernel<<<nsamples, THREADS, smem_bytes>>>(x, w1, w2, w3, wfc,
                                                        (float*)d_out);
}

// round 17
// speedup vs baseline: 1.0320x; 1.0320x over previous
#include <cuda_runtime.h>

// SmartDoorClassifierv1 — fused CNN (LIF collapses: alpha = exp(-200) == 0 in fp32).
// Round 16: kernel is at the scalar-FFMA throughput wall (32M warp-FFMA x rt2
// == R12's duration). Reduce fma-pipe ops: Winograd F(2x2,3x3) on stage 2 with
// INTEGER input transform (p1 activations are exact small ints; B entries are
// 0/±1 -> transform runs exact on the ALU pipe). Stage-2 fma 2304 -> 1216.
// p1 stored int32; weights pre-transformed (GgG^T) once per CTA.
// max-before-floor everywhere (exact: max commutes with monotone floor/relu).

#define THREADS 256

// dynamic smem layout (word indices; p1i is int, rest float)
//  p1i  : 8 x 34 x 36 = 9792  (stage-1 pooled INT, 1-halo, row stride 36)
//  p2p  : 8 x 18 x 18 = 2592  (stage-2 pooled float, 1-halo)
//  p3   : 512
//  sw1  : 64
//  Uw   : 1024  transformed stage-2 weights, layout (ic*16 + i)*8 + oc
//  sw3p : 796   (oc stride 100, per-ic stride 12)
//  red  : 16
#define OFF_P1   0
#define OFF_P2   9792
#define OFF_P3   12384
#define OFF_W1   12896
#define OFF_UW   12960
#define OFF_W3   13984
#define OFF_RED  14780
#define SMEM_WORDS (OFF_RED + 16)   // 14796 words = 59184 B

#define P1_RS   36
#define P1_PL   1224      // 34 rows * 36
#define P2_RS   18
#define P2_PL   324

__global__ __launch_bounds__(THREADS, 2)
void snn_fused_kernel(const float* __restrict__ x,
                      const float* __restrict__ w1,
                      const float* __restrict__ w2,
                      const float* __restrict__ w3,
                      const float* __restrict__ wfc,
                      float* __restrict__ out)
{
    extern __shared__ float smem[];
    int*   p1i  = reinterpret_cast<int*>(smem + OFF_P1);
    float* p2p  = smem + OFF_P2;
    float* p3   = smem + OFF_P3;
    float* sw1  = smem + OFF_W1;
    float* Uw   = smem + OFF_UW;
    float* sw3p = smem + OFF_W3;
    float* red  = smem + OFF_RED;

    const int tid = threadIdx.x;
    const int n   = blockIdx.x;

    // ---- init: sw1, transformed U = G g G^T for w2, padded sw3, halos ----
    if (tid < 64) sw1[tid] = w1[tid];
    if (tid < 64) {
        int oc = tid >> 3, ic = tid & 7;
        const float* g = w2 + (oc * 8 + ic) * 9;   // g[ky*3+kx]
        float z[4][3];
        #pragma unroll
        for (int c = 0; c < 3; c++) {
            float g0 = g[c], g1 = g[3 + c], g2 = g[6 + c];
            z[0][c] = g0;
            z[1][c] = 0.5f * (g0 + g1 + g2);
            z[2][c] = 0.5f * (g0 - g1 + g2);
            z[3][c] = g2;
        }
        #pragma unroll
        for (int r = 0; r < 4; r++) {
            float u0 = z[r][0], u1 = z[r][1], u2 = z[r][2];
            float U0 = u0;
            float U1 = 0.5f * (u0 + u1 + u2);
            float U2 = 0.5f * (u0 - u1 + u2);
            float U3 = u2;
            Uw[(ic * 16 + r * 4 + 0) * 8 + oc] = U0;
            Uw[(ic * 16 + r * 4 + 1) * 8 + oc] = U1;
            Uw[(ic * 16 + r * 4 + 2) * 8 + oc] = U2;
            Uw[(ic * 16 + r * 4 + 3) * 8 + oc] = U3;
        }
    }
    for (int i = tid; i < 576; i += THREADS) {
        int oc = i / 72, rem = i % 72, ic = rem / 9, k = rem % 9;
        sw3p[oc * 100 + ic * 12 + k] = w3[i];
    }
    // p1i halos (int 0)
    for (int i = tid; i < 8 * 34; i += THREADS) {
        int ic = i / 34, c = i % 34;
        p1i[ic * P1_PL + c] = 0;
        p1i[ic * P1_PL + 33 * P1_RS + c] = 0;
    }
    for (int i = tid; i < 8 * 32; i += THREADS) {
        int ic = i / 32, r = (i % 32) + 1;
        p1i[ic * P1_PL + r * P1_RS] = 0;
        p1i[ic * P1_PL + r * P1_RS + 33] = 0;
    }
    // p2p halos
    for (int i = tid; i < 8 * 18; i += THREADS) {
        int ic = i / 18, c = i % 18;
        p2p[ic * P2_PL + c] = 0.f;
        p2p[ic * P2_PL + 17 * P2_RS + c] = 0.f;
    }
    for (int i = tid; i < 8 * 16; i += THREADS) {
        int ic = i / 16, r = (i % 16) + 1;
        p2p[ic * P2_PL + r * P2_RS] = 0.f;
        p2p[ic * P2_PL + r * P2_RS + 17] = 0.f;
    }
    __syncthreads();

    // ================= Stage 1: conv1(2x2,s2) + max + relu + trunc -> int ===
    const float* xb = x + (size_t)n * (2 * 128 * 128);
    #pragma unroll 1
    for (int it = 0; it < 4; it++) {
        int pos = tid + it * THREADS;          // 0..1023
        int py = pos >> 5, px = pos & 31;
        const float* src0 = xb + (4 * py) * 128 + 4 * px;   // ch0
        const float* src1 = src0 + 16384;                   // ch1
        float4 c0r0 = *reinterpret_cast<const float4*>(src0);
        float4 c0r1 = *reinterpret_cast<const float4*>(src0 + 128);
        float4 c0r2 = *reinterpret_cast<const float4*>(src0 + 256);
        float4 c0r3 = *reinterpret_cast<const float4*>(src0 + 384);
        float4 c1r0 = *reinterpret_cast<const float4*>(src1);
        float4 c1r1 = *reinterpret_cast<const float4*>(src1 + 128);
        float4 c1r2 = *reinterpret_cast<const float4*>(src1 + 256);
        float4 c1r3 = *reinterpret_cast<const float4*>(src1 + 384);

        int* dst = p1i + (py + 1) * P1_RS + (px + 1);
        #pragma unroll
        for (int oc = 0; oc < 8; oc++) {
            const float* wb = sw1 + oc * 8;
            float4 wA = *reinterpret_cast<const float4*>(wb);      // ch0 2x2
            float4 wB = *reinterpret_cast<const float4*>(wb + 4);  // ch1 2x2
            float v00, v01, v10, v11;
            v00 = c0r0.x * wA.x;               v01 = c0r0.z * wA.x;
            v00 = fmaf(c0r0.y, wA.y, v00);     v01 = fmaf(c0r0.w, wA.y, v01);
            v00 = fmaf(c0r1.x, wA.z, v00);     v01 = fmaf(c0r1.z, wA.z, v01);
            v00 = fmaf(c0r1.y, wA.w, v00);     v01 = fmaf(c0r1.w, wA.w, v01);
            v00 = fmaf(c1r0.x, wB.x, v00);     v01 = fmaf(c1r0.z, wB.x, v01);
            v00 = fmaf(c1r0.y, wB.y, v00);     v01 = fmaf(c1r0.w, wB.y, v01);
            v00 = fmaf(c1r1.x, wB.z, v00);     v01 = fmaf(c1r1.z, wB.z, v01);
            v00 = fmaf(c1r1.y, wB.w, v00);     v01 = fmaf(c1r1.w, wB.w, v01);

            v10 = c0r2.x * wA.x;               v11 = c0r2.z * wA.x;
            v10 = fmaf(c0r2.y, wA.y, v10);     v11 = fmaf(c0r2.w, wA.y, v11);
            v10 = fmaf(c0r3.x, wA.z, v10);     v11 = fmaf(c0r3.z, wA.z, v11);
            v10 = fmaf(c0r3.y, wA.w, v10);     v11 = fmaf(c0r3.w, wA.w, v11);
            v10 = fmaf(c1r2.x, wB.x, v10);     v11 = fmaf(c1r2.z, wB.x, v11);
            v10 = fmaf(c1r2.y, wB.y, v10);     v11 = fmaf(c1r2.w, wB.y, v11);
            v10 = fmaf(c1r3.x, wB.z, v10);     v11 = fmaf(c1r3.z, wB.z, v11);
            v10 = fmaf(c1r3.y, wB.w, v10);     v11 = fmaf(c1r3.w, wB.w, v11);

            // max commutes with monotone floor/relu; trunc == floor for >=0
            float mx = fmaxf(fmaxf(v00, v01), fmaxf(v10, v11));
            dst[oc * P1_PL] = (int)fmaxf(mx, 0.f);
        }
    }
    __syncthreads();

    // ================= Stage 2: Winograd F(2x2,3x3) + max + relu + floor ====
    // Thread = 1 pooled pos; two passes over oc quads (ocg = 0,1).
    // IT exact in int on ALU pipe; EW 16 FFMA/tile; OT 24 FADD/oc.
    {
        int py = tid >> 4, px = tid & 15;
        const int* pbase = p1i + (2 * py) * P1_RS + 2 * px;
        float* dst = p2p + (py + 1) * P2_RS + (px + 1);

        #pragma unroll 1
        for (int ocg = 0; ocg < 2; ocg++) {
            float acc[4][16];
            #pragma unroll
            for (int o = 0; o < 4; o++)
                #pragma unroll
                for (int i = 0; i < 16; i++) acc[o][i] = 0.f;

            #pragma unroll 1
            for (int ic = 0; ic < 8; ic++) {
                const int* base = pbase + ic * P1_PL;
                int d[4][4];
                #pragma unroll
                for (int r = 0; r < 4; r++) {
                    int2 a = *reinterpret_cast<const int2*>(base + r * P1_RS);
                    int2 b = *reinterpret_cast<const int2*>(base + r * P1_RS + 2);
                    d[r][0] = a.x; d[r][1] = a.y; d[r][2] = b.x; d[r][3] = b.y;
                }
                // z = B^T d  (rows), V = z B (cols) — exact integer adds
                int z[4][4];
                #pragma unroll
                for (int c = 0; c < 4; c++) {
                    z[0][c] = d[0][c] - d[2][c];
                    z[1][c] = d[1][c] + d[2][c];
                    z[2][c] = d[2][c] - d[1][c];
                    z[3][c] = d[1][c] - d[3][c];
                }
                int V[16];
                #pragma unroll
                for (int r = 0; r < 4; r++) {
                    V[r * 4 + 0] = z[r][0] - z[r][2];
                    V[r * 4 + 1] = z[r][1] + z[r][2];
                    V[r * 4 + 2] = z[r][2] - z[r][1];
                    V[r * 4 + 3] = z[r][1] - z[r][3];
                }
                const float* ub = Uw + ic * 128 + ocg * 4;
                #pragma unroll
                for (int i = 0; i < 16; i++) {
                    float vf = __int2float_rn(V[i]);
                    float4 u = *reinterpret_cast<const float4*>(ub + i * 8);
                    acc[0][i] = fmaf(vf, u.x, acc[0][i]);
                    acc[1][i] = fmaf(vf, u.y, acc[1][i]);
                    acc[2][i] = fmaf(vf, u.z, acc[2][i]);
                    acc[3][i] = fmaf(vf, u.w, acc[3][i]);
                }
            }
            // Output transform Y = A^T m A, then max/relu/floor
            #pragma unroll
            for (int o = 0; o < 4; o++) {
                float z0[4], z1[4];
                #pragma unroll
                for (int c = 0; c < 4; c++) {
                    float m0 = acc[o][c], m1 = acc[o][4 + c];
                    float m2 = acc[o][8 + c], m3 = acc[o][12 + c];
                    z0[c] = m0 + m1 + m2;
                    z1[c] = m1 - m2 - m3;
                }
                float Y00 = z0[0] + z0[1] + z0[2];
                float Y01 = z0[1] - z0[2] - z0[3];
                float Y10 = z1[0] + z1[1] + z1[2];
                float Y11 = z1[1] - z1[2] - z1[3];
                float mx = fmaxf(fmaxf(Y00, Y01), fmaxf(Y10, Y11));
                dst[(ocg * 4 + o) * P2_PL] = floorf(fmaxf(mx, 0.f));
            }
        }
    }
    __syncthreads();

    // ================= Stage 3: conv3(3x3,p2) direct + max + relu + floor ===
    {
        int pos = tid >> 2;                // 0..63
        int ocg = tid & 3;
        int py = pos >> 3, px = pos & 7;
        float acc[2][2][2];
        #pragma unroll
        for (int j = 0; j < 2; j++)
            #pragma unroll
            for (int a = 0; a < 2; a++)
                #pragma unroll
                for (int b = 0; b < 2; b++) acc[j][a][b] = 0.f;

        #pragma unroll 1
        for (int ic = 0; ic < 8; ic++) {
            const float* base = p2p + ic * P2_PL + (2 * py) * P2_RS + 2 * px;
            float patch[4][4];
            #pragma unroll
            for (int r = 0; r < 4; r++) {
                float2 a = *reinterpret_cast<const float2*>(base + r * P2_RS);
                float2 b = *reinterpret_cast<const float2*>(base + r * P2_RS + 2);
                patch[r][0] = a.x; patch[r][1] = a.y;
                patch[r][2] = b.x; patch[r][3] = b.y;
            }
            #pragma unroll
            for (int j = 0; j < 2; j++) {
                const float* wb = sw3p + (ocg * 2 + j) * 100 + ic * 12;
                float4 wA = *reinterpret_cast<const float4*>(wb);
                float4 wB = *reinterpret_cast<const float4*>(wb + 4);
                float w8 = wb[8];
                #pragma unroll
                for (int dy = 0; dy < 2; dy++) {
                    #pragma unroll
                    for (int dx = 0; dx < 2; dx++) {
                        float a = acc[j][dy][dx];
                        a = fmaf(patch[dy + 0][dx + 0], wA.x, a);
                        a = fmaf(patch[dy + 0][dx + 1], wA.y, a);
                        a = fmaf(patch[dy + 0][dx + 2], wA.z, a);
                        a = fmaf(patch[dy + 1][dx + 0], wA.w, a);
                        a = fmaf(patch[dy + 1][dx + 1], wB.x, a);
                        a = fmaf(patch[dy + 1][dx + 2], wB.y, a);
                        a = fmaf(patch[dy + 2][dx + 0], wB.z, a);
                        a = fmaf(patch[dy + 2][dx + 1], wB.w, a);
                        a = fmaf(patch[dy + 2][dx + 2], w8,   a);
                        acc[j][dy][dx] = a;
                    }
                }
            }
        }
        #pragma unroll
        for (int j = 0; j < 2; j++) {
            int oc = ocg * 2 + j;
            float mx = fmaxf(fmaxf(acc[j][0][0], acc[j][0][1]),
                             fmaxf(acc[j][1][0], acc[j][1][1]));
            p3[oc * 64 + py * 8 + px] = floorf(fmaxf(mx, 0.f));
        }
    }
    __syncthreads();

    // ================= Stage 4: fc (512 -> 2) ===============================
    {
        float a0 = 0.f, a1 = 0.f;
        #pragma unroll
        for (int k = 0; k < 2; k++) {
            int j = tid + k * THREADS;         // 0..511
            float v = p3[j];
            a0 = fmaf(v, wfc[j],       a0);
            a1 = fmaf(v, wfc[512 + j], a1);
        }
        #pragma unroll
        for (int off = 16; off > 0; off >>= 1) {
            a0 += __shfl_down_sync(0xffffffffu, a0, off);
            a1 += __shfl_down_sync(0xffffffffu, a1, off);
        }
        if ((tid & 31) == 0) {
            red[tid >> 5]       = a0;
            red[8 + (tid >> 5)] = a1;
        }
        __syncthreads();
        if (tid == 0) {
            float s0 = 0.f, s1 = 0.f;
            #pragma unroll
            for (int i = 0; i < 8; i++) { s0 += red[i]; s1 += red[8 + i]; }
            out[n * 2 + 0] = s0;
            out[n * 2 + 1] = s1;
        }
    }
}

extern "C" void kernel_launch(void* const* d_in, const int* in_sizes, int n_in,
                              void* d_out, int out_size)
{
    const float* x   = (const float*)d_in[0];
    const float* w1  = (const float*)d_in[1];
    const float* w2  = (const float*)d_in[2];
    const float* w3  = (const float*)d_in[3];
    const float* wfc = (const float*)d_in[4];
    int nsamples = in_sizes[0] / (2 * 128 * 128);   // 1024

    size_t smem_bytes = SMEM_WORDS * sizeof(float);  // 59184 B (~57.8 KB)
    cudaFuncSetAttribute(snn_fused_kernel,
                         cudaFuncAttributeMaxDynamicSharedMemorySize,
                         (int)smem_bytes);
    snn_fused_kernel<<<nsamples, THREADS, smem_bytes>>>(x, w1, w2, w3, wfc,
                                                        (float*)d_out);
}